// round 15
// baseline (speedup 1.0000x reference)
#include <cuda_runtime.h>
#include <cuda_fp16.h>
#include <cstdint>
#include <cstddef>

// Problem constants
#define BB    4
#define CIN   256
#define HH    56
#define WW    56
#define COUT  256
#define KK9   9
#define OCH   18
#define MOFF  32              // padded M for offset GEMM
#define P     (HH*WW)         // 3136
#define NTOT  (BB*P)          // 12544
#define KDIM  (CIN*KK9)       // 2304

// sample ci split
#define CISPL  2
#define CIH    (CIN/CISPL)    // 128

// Main GEMM tiling (fp16 single pass): proven config
#define BM   128
#define BN   64
#define BK   64
#define NKC  (KDIM/BK)    // 36

#define A_ROWB 144
#define B_ROWB 144
#define A_PLANE (BM*A_ROWB)          // 18432
#define B_PLANE (BK*B_ROWB)          // 9216
#define B_OFF   A_PLANE
#define BUF_BYTES (A_PLANE+B_PLANE)  // 27648
#define SMEM_TOTAL (2*BUF_BYTES)     // 55296

// Offset GEMM (implicit im2col): M=32, N=64, K chunks of 64 (one kk per chunk)
#define OA_PLANE (MOFF*A_ROWB)       // 4608
#define OIDX_BYTES (KK9*64*4)        // 2304
#define OA0_OFF  OIDX_BYTES          // 2304
#define OA1_OFF  (OIDX_BYTES+OA_PLANE)
#define OB_SOFF  (OIDX_BYTES+2*OA_PLANE)       // 11520
#define OSMEM_TOTAL (OB_SOFF+B_PLANE)          // 20736

// Scratch (device globals)
__device__ __align__(16) __half g_S [(size_t)KDIM * NTOT];  // deformed samples
__device__ __align__(16) __half g_W[COUT * KDIM];
__device__ __align__(16) __half g_Woff[MOFF * KDIM];        // K-permuted: k'=kk*CIN+ci
__device__ __align__(16) float  g_Off[OCH * NTOT];          // final offsets

// ---------------------------------------------------------------------------
// helpers
// ---------------------------------------------------------------------------
__device__ __forceinline__ uint32_t smem_u32(const void* p) {
    uint32_t a;
    asm("{ .reg .u64 t; cvta.to.shared.u64 t, %1; cvt.u32.u64 %0, t; }" : "=r"(a) : "l"(p));
    return a;
}
__device__ __forceinline__ void cp16(uint32_t dst, const void* src) {
    asm volatile("cp.async.ca.shared.global [%0], [%1], 16;" :: "r"(dst), "l"(src) : "memory");
}
__device__ __forceinline__ void cp_commit() {
    asm volatile("cp.async.commit_group;" ::: "memory");
}
__device__ __forceinline__ void cp_wait1() {
    asm volatile("cp.async.wait_group 1;" ::: "memory");
}
__device__ __forceinline__ void cp_wait0() {
    asm volatile("cp.async.wait_group 0;" ::: "memory");
}
__device__ __forceinline__ void ldsm_x4(uint32_t* r, uint32_t addr) {
    asm volatile("ldmatrix.sync.aligned.m8n8.x4.shared.b16 {%0,%1,%2,%3}, [%4];"
                 : "=r"(r[0]), "=r"(r[1]), "=r"(r[2]), "=r"(r[3]) : "r"(addr));
}
__device__ __forceinline__ void ldsm_x4t(uint32_t* r, uint32_t addr) {
    asm volatile("ldmatrix.sync.aligned.m8n8.x4.trans.shared.b16 {%0,%1,%2,%3}, [%4];"
                 : "=r"(r[0]), "=r"(r[1]), "=r"(r[2]), "=r"(r[3]) : "r"(addr));
}
__device__ __forceinline__ void mma_f16(float* c, const uint32_t* a, uint32_t b0, uint32_t b1) {
    asm volatile("mma.sync.aligned.m16n8k16.row.col.f32.f16.f16.f32 "
                 "{%0,%1,%2,%3}, {%4,%5,%6,%7}, {%8,%9}, {%0,%1,%2,%3};"
                 : "+f"(c[0]), "+f"(c[1]), "+f"(c[2]), "+f"(c[3])
                 : "r"(a[0]), "r"(a[1]), "r"(a[2]), "r"(a[3]), "r"(b0), "r"(b1));
}

// ---------------------------------------------------------------------------
// Kernel 0a: main weights -> fp16
// ---------------------------------------------------------------------------
__global__ __launch_bounds__(256) void wconv_kernel(const float* __restrict__ w) {
    int i = blockIdx.x * 256 + threadIdx.x;
    if (i >= COUT * KDIM) return;
    g_W[i] = __float2half_rn(w[i]);
}

// Kernel 0b: offset weights -> fp16, K-permuted (k' = kk*CIN + ci), padded rows
__global__ __launch_bounds__(256) void wcvt_off_kernel(const float* __restrict__ ow) {
    int i = blockIdx.x * 256 + threadIdx.x;
    if (i >= MOFF * KDIM) return;
    int oc = i / KDIM;
    int kp = i % KDIM;
    int kk = kp / CIN;
    int ci = kp % CIN;
    float v = (oc < OCH) ? ow[((size_t)(oc * CIN + ci)) * KK9 + kk] : 0.0f;
    g_Woff[i] = __float2half_rn(v);
}

// ---------------------------------------------------------------------------
// Kernel 1: offset GEMM with implicit im2col B (reads x directly, L2-resident).
// g_Off[oc][n] = sum_k Woff[oc][k'] * x_shift[k'][n] + off_b[oc]
// 256 threads: all load, warps 0..3 compute (each one n16 tile).
// ---------------------------------------------------------------------------
__global__ __launch_bounds__(256) void offgemm_kernel(
    const float* __restrict__ x, const float* __restrict__ off_b)
{
    extern __shared__ char smem[];
    const uint32_t sb = smem_u32(smem);
    int* idxs = (int*)smem;
    const int tid  = threadIdx.x;
    const int wid  = tid >> 5;
    const int lane = tid & 31;
    const int n0   = blockIdx.x * BN;
    const int bidx = n0 / P;
    const int p0   = n0 % P;

    // Precompute shifted indices for all 9 taps x 64 cols (-1 = out of bounds)
    for (int i = tid; i < KK9 * 64; i += 256) {
        int kk = i >> 6, c = i & 63;
        int p  = p0 + c;
        int y  = p / WW, xx = p % WW;
        int ny = y + kk / 3 - 1;
        int nx = xx + kk % 3 - 1;
        idxs[i] = (ny >= 0 && ny < HH && nx >= 0 && nx < WW) ? (ny * WW + nx) : -1;
    }

    float acc[2][2][4];
#pragma unroll
    for (int i = 0; i < 2; i++)
#pragma unroll
        for (int j = 0; j < 2; j++)
#pragma unroll
            for (int q = 0; q < 4; q++) acc[i][j][q] = 0.0f;

    const int lrow  = lane & 15;
    const int lhalf = lane >> 4;
    const uint32_t a_base = (uint32_t)lrow * A_ROWB + lhalf * 16;
    const uint32_t b_base = OB_SOFF + (uint32_t)lrow * B_ROWB
                          + (uint32_t)(wid * 16 + lhalf * 8) * 2;

    // A loader: 32 rows x 8 granules = 256 cp16, exactly 1/thread
    const int awr = tid >> 3, awc = tid & 7;
    auto loadA = [&](uint32_t aoff, int k0) {
        cp16(sb + aoff + awr * A_ROWB + awc * 16,
             g_Woff + (size_t)awr * KDIM + k0 + awc * 8);
    };

    // B loader thread mapping: 4 iterations x (16 rows x 16 col-quads)
    const int brq = tid >> 4;          // row within 16-row group
    const int bcq = (tid & 15) * 4;    // col base (4 cols)
    const float* xb = x + (size_t)bidx * CIN * P;

    loadA(OA0_OFF, 0);
    cp_commit();
    __syncthreads();   // idxs ready

#pragma unroll 1
    for (int kc = 0; kc < NKC; kc++) {
        const int kk  = kc >> 2;
        const int ci0 = (kc & 3) << 6;
        if (kc) __syncthreads();       // prior compute done before B overwrite

        // B: implicit im2col load (16 LDG.32 + 4 STS.64 per thread)
        const int4 id4 = *(const int4*)(idxs + kk * 64 + bcq);
#pragma unroll
        for (int it = 0; it < 4; it++) {
            int r  = it * 16 + brq;
            const float* xr = xb + (size_t)(ci0 + r) * P;
            float v0 = (id4.x >= 0) ? __ldg(xr + id4.x) : 0.0f;
            float v1 = (id4.y >= 0) ? __ldg(xr + id4.y) : 0.0f;
            float v2 = (id4.z >= 0) ? __ldg(xr + id4.z) : 0.0f;
            float v3 = (id4.w >= 0) ? __ldg(xr + id4.w) : 0.0f;
            __half2 h0 = __floats2half2_rn(v0, v1);
            __half2 h1 = __floats2half2_rn(v2, v3);
            *(__half2*)(smem + OB_SOFF + r * B_ROWB + bcq * 2)     = h0;
            *(__half2*)(smem + OB_SOFF + r * B_ROWB + bcq * 2 + 4) = h1;
        }

        if (kc < NKC - 1) {
            loadA((uint32_t)(((kc + 1) & 1) ? OA1_OFF : OA0_OFF), (kc + 1) * BK);
            cp_commit();
            cp_wait1();
        } else {
            cp_wait0();
        }
        __syncthreads();

        if (wid < 4) {
            const uint32_t abuf = (kc & 1) ? OA1_OFF : OA0_OFF;
#pragma unroll
            for (int ks = 0; ks < 4; ks++) {
                uint32_t A[2][4], B[4];
#pragma unroll
                for (int mt = 0; mt < 2; mt++)
                    ldsm_x4(A[mt], sb + abuf + a_base + (uint32_t)mt * 16 * A_ROWB + ks * 32);
                ldsm_x4t(B, sb + b_base + (uint32_t)ks * 16 * B_ROWB);
#pragma unroll
                for (int mt = 0; mt < 2; mt++)
#pragma unroll
                    for (int h = 0; h < 2; h++)
                        mma_f16(acc[mt][h], A[mt], B[2*h], B[2*h+1]);
            }
        }
    }

    if (wid < 4) {
        const int g = lane >> 2;
        const int t = lane & 3;
#pragma unroll
        for (int mt = 0; mt < 2; mt++) {
            int r0 = mt * 16 + g;
            int r1 = r0 + 8;
            float b0 = (r0 < OCH) ? off_b[r0] : 0.0f;
            float b1 = (r1 < OCH) ? off_b[r1] : 0.0f;
#pragma unroll
            for (int nt = 0; nt < 2; nt++) {
                int col = n0 + wid * 16 + nt * 8 + 2 * t;
                if (r0 < OCH) {
                    g_Off[(size_t)r0 * NTOT + col]     = acc[mt][nt][0] + b0;
                    g_Off[(size_t)r0 * NTOT + col + 1] = acc[mt][nt][1] + b0;
                }
                if (r1 < OCH) {
                    g_Off[(size_t)r1 * NTOT + col]     = acc[mt][nt][2] + b1;
                    g_Off[(size_t)r1 * NTOT + col + 1] = acc[mt][nt][3] + b1;
                }
            }
        }
    }
}

// ---------------------------------------------------------------------------
// Kernel 2: bilinear sampling -> fp16 S[k=ci*9+kk][n=b*P+p]
// ---------------------------------------------------------------------------
__global__ __launch_bounds__(256) void sample_kernel(const float* __restrict__ x)
{
    const int tid = threadIdx.x;
    const int p   = blockIdx.x * 256 + tid;
    if (p >= P) return;
    const int b   = blockIdx.y;
    const int kk  = blockIdx.z / CISPL;
    const int ci0 = (blockIdx.z % CISPL) * CIH;

    const int n = b * P + p;
    const float offy = __ldg(g_Off + (size_t)(2 * kk)     * NTOT + n);
    const float offx = __ldg(g_Off + (size_t)(2 * kk + 1) * NTOT + n);

    const int ho = p / WW;
    const int wo = p % WW;
    const float py = (float)(ho - 1 + kk / 3) + offy;
    const float px = (float)(wo - 1 + kk % 3) + offx;
    const float fy = floorf(py), fx = floorf(px);
    const int y0 = (int)fy, x0 = (int)fx;
    const int y1 = y0 + 1,  x1 = x0 + 1;
    const float ty = py - fy, tx = px - fx;

    float w00 = (1.0f - ty) * (1.0f - tx);
    float w01 = (1.0f - ty) * tx;
    float w10 = ty * (1.0f - tx);
    float w11 = ty * tx;

    const bool vy0 = (y0 >= 0 && y0 < HH), vy1 = (y1 >= 0 && y1 < HH);
    const bool vx0 = (x0 >= 0 && x0 < WW), vx1 = (x1 >= 0 && x1 < WW);
    w00 *= (vy0 && vx0) ? 1.0f : 0.0f;
    w01 *= (vy0 && vx1) ? 1.0f : 0.0f;
    w10 *= (vy1 && vx0) ? 1.0f : 0.0f;
    w11 *= (vy1 && vx1) ? 1.0f : 0.0f;

    const int cy0 = min(max(y0, 0), HH - 1), cy1 = min(max(y1, 0), HH - 1);
    const int cx0 = min(max(x0, 0), WW - 1), cx1 = min(max(x1, 0), WW - 1);
    const int i00 = cy0 * WW + cx0, i01 = cy0 * WW + cx1;
    const int i10 = cy1 * WW + cx0, i11 = cy1 * WW + cx1;

    const float* xb = x + ((size_t)(b * CIN + ci0)) * P;
    const size_t base = (size_t)(ci0 * KK9 + kk) * NTOT + (size_t)n;
    const size_t srow = (size_t)KK9 * NTOT;

#pragma unroll 8
    for (int ci = 0; ci < CIH; ci++) {
        const float* xc = xb + (size_t)ci * P;
        float v = w00 * __ldg(xc + i00) + w01 * __ldg(xc + i01)
                + w10 * __ldg(xc + i10) + w11 * __ldg(xc + i11);
        g_S[base + (size_t)ci * srow] = __float2half_rn(v);
    }
}

// ---------------------------------------------------------------------------
// Kernel 3: main fp16 GEMM (proven config).
// ---------------------------------------------------------------------------
__global__ __launch_bounds__(128, 3) void gemm_mma_kernel(float* __restrict__ out)
{
    extern __shared__ char smem[];
    const uint32_t sb = smem_u32(smem);
    const int tid  = threadIdx.x;
    const int wid  = tid >> 5;
    const int lane = tid & 31;
    const int wm   = wid & 1;
    const int wn   = wid >> 1;
    const int n0   = blockIdx.x * BN;
    const int m0   = blockIdx.y * BM;

    float acc[4][4][4];
#pragma unroll
    for (int i = 0; i < 4; i++)
#pragma unroll
        for (int j = 0; j < 4; j++)
#pragma unroll
            for (int q = 0; q < 4; q++) acc[i][j][q] = 0.0f;

    const __half* pW = g_W + (size_t)m0 * KDIM;
    const __half* pS = g_S + n0;

    const int lrow  = lane & 15;
    const int lhalf = lane >> 4;
    const uint32_t a_base = (uint32_t)(wm * 64 + lrow) * A_ROWB + lhalf * 16;
    const uint32_t b_base = (uint32_t)lrow * B_ROWB + (uint32_t)(wn * 32 + lhalf * 8) * 2;

    auto load_stage = [&](uint32_t st, int k0) {
#pragma unroll
        for (int it = 0; it < 8; it++) {
            int idx = it * 128 + tid;
            int row = idx >> 3;
            int c   = idx & 7;
            cp16(st + row * A_ROWB + c * 16, pW + (size_t)row * KDIM + k0 + c * 8);
        }
#pragma unroll
        for (int it = 0; it < 4; it++) {
            int idx = it * 128 + tid;
            int row = idx >> 3;
            int c   = idx & 7;
            cp16(st + B_OFF + row * B_ROWB + c * 16, pS + (size_t)(k0 + row) * NTOT + c * 8);
        }
    };

    load_stage(sb, 0);
    cp_commit();

#pragma unroll 1
    for (int kc = 0; kc < NKC; kc++) {
        const uint32_t buf = sb + (uint32_t)(kc & 1) * BUF_BYTES;
        if (kc < NKC - 1) {
            load_stage(sb + (uint32_t)((kc + 1) & 1) * BUF_BYTES, (kc + 1) * BK);
            cp_commit();
            cp_wait1();
        } else {
            cp_wait0();
        }
        __syncthreads();

#pragma unroll
        for (int kk = 0; kk < 4; kk++) {
            uint32_t A[4][4], B[2][4];
#pragma unroll
            for (int mt = 0; mt < 4; mt++)
                ldsm_x4(A[mt], buf + a_base + (uint32_t)mt * 16 * A_ROWB + kk * 32);
#pragma unroll
            for (int bq = 0; bq < 2; bq++)
                ldsm_x4t(B[bq], buf + B_OFF + b_base + (uint32_t)kk * 16 * B_ROWB + bq * 32);
#pragma unroll
            for (int mt = 0; mt < 4; mt++) {
#pragma unroll
                for (int bq = 0; bq < 2; bq++) {
#pragma unroll
                    for (int h = 0; h < 2; h++) {
                        int nt = bq * 2 + h;
                        mma_f16(acc[mt][nt], A[mt], B[bq][2*h], B[bq][2*h+1]);
                    }
                }
            }
        }
        __syncthreads();
    }

    const int g = lane >> 2;
    const int t = lane & 3;
    const int bidx = n0 / P;
    const int pofs = n0 % P;
#pragma unroll
    for (int mt = 0; mt < 4; mt++) {
        int mrow = m0 + wm * 64 + mt * 16 + g;
        float* r0 = out + ((size_t)(bidx * COUT + mrow)) * P + pofs;
        float* r1 = r0 + 8 * P;
#pragma unroll
        for (int nt = 0; nt < 4; nt++) {
            int col = wn * 32 + nt * 8 + 2 * t;
            *(float2*)(r0 + col) = make_float2(acc[mt][nt][0], acc[mt][nt][1]);
            *(float2*)(r1 + col) = make_float2(acc[mt][nt][2], acc[mt][nt][3]);
        }
    }
}

// ---------------------------------------------------------------------------
extern "C" void kernel_launch(void* const* d_in, const int* in_sizes, int n_in,
                              void* d_out, int out_size)
{
    const float* x     = (const float*)d_in[0];
    const float* wgt   = (const float*)d_in[1];
    const float* off_w = (const float*)d_in[2];
    const float* off_b = (const float*)d_in[3];
    float* out = (float*)d_out;

    cudaFuncSetAttribute(gemm_mma_kernel, cudaFuncAttributeMaxDynamicSharedMemorySize, SMEM_TOTAL);
    cudaFuncSetAttribute(offgemm_kernel, cudaFuncAttributeMaxDynamicSharedMemorySize, OSMEM_TOTAL);

    wconv_kernel<<<(COUT * KDIM + 255) / 256, 256>>>(wgt);
    wcvt_off_kernel<<<(MOFF * KDIM + 255) / 256, 256>>>(off_w);

    offgemm_kernel<<<NTOT / BN, 256, OSMEM_TOTAL>>>(x, off_b);

    dim3 g2((P + 255) / 256, BB, KK9 * CISPL);
    sample_kernel<<<g2, 256>>>(x);

    dim3 g3(NTOT / BN, COUT / BM);
    gemm_mma_kernel<<<g3, 128, SMEM_TOTAL>>>(out);
}

// round 16
// speedup vs baseline: 1.1157x; 1.1157x over previous
#include <cuda_runtime.h>
#include <cuda_fp16.h>
#include <cstdint>
#include <cstddef>

// Problem constants
#define BB    4
#define CIN   256
#define HH    56
#define WW    56
#define COUT  256
#define KK9   9
#define OCH   18
#define MOFF  32              // padded M for offset GEMM
#define P     (HH*WW)         // 3136
#define NTOT  (BB*P)          // 12544
#define KDIM  (CIN*KK9)       // 2304

// sample / s0 ci split
#define CISPL  2
#define CIH    (CIN/CISPL)    // 128

// offset GEMM K split
#define KSPL   2
#define NKCH   (KDIM/64/KSPL) // 18 chunks per split

// Main GEMM tiling (fp16 single pass): proven config
#define BM   128
#define BN   64
#define BK   64
#define NKC  (KDIM/BK)    // 36

#define A_ROWB 144
#define B_ROWB 144
#define A_PLANE (BM*A_ROWB)          // 18432
#define B_PLANE (BK*B_ROWB)          // 9216
#define B_OFF   A_PLANE
#define BUF_BYTES (A_PLANE+B_PLANE)  // 27648
#define SMEM_TOTAL (2*BUF_BYTES)     // 55296

// Offset GEMM tiling: M=32, N=64, K=64
#define OA_PLANE (MOFF*A_ROWB)       // 4608
#define OB_OFF   OA_PLANE
#define OBUF_BYTES (OA_PLANE+B_PLANE) // 13824
#define OSMEM_TOTAL (2*OBUF_BYTES)    // 27648

// Scratch (device globals)
__device__ __align__(16) __half g_S [(size_t)KDIM * NTOT];  // deformed samples
__device__ __align__(16) __half g_S0[(size_t)KDIM * NTOT];  // zero-offset im2col
__device__ __align__(16) __half g_W[COUT * KDIM];
__device__ __align__(16) __half g_Woff[MOFF * KDIM];        // rows 18..31 zero
__device__ __align__(16) float  g_OffP[KSPL * OCH * NTOT];  // partial offsets

// ---------------------------------------------------------------------------
// helpers
// ---------------------------------------------------------------------------
__device__ __forceinline__ uint32_t smem_u32(const void* p) {
    uint32_t a;
    asm("{ .reg .u64 t; cvta.to.shared.u64 t, %1; cvt.u32.u64 %0, t; }" : "=r"(a) : "l"(p));
    return a;
}
__device__ __forceinline__ void cp16(uint32_t dst, const void* src) {
    asm volatile("cp.async.ca.shared.global [%0], [%1], 16;" :: "r"(dst), "l"(src) : "memory");
}
__device__ __forceinline__ void cp_commit() {
    asm volatile("cp.async.commit_group;" ::: "memory");
}
__device__ __forceinline__ void cp_wait1() {
    asm volatile("cp.async.wait_group 1;" ::: "memory");
}
__device__ __forceinline__ void cp_wait0() {
    asm volatile("cp.async.wait_group 0;" ::: "memory");
}
__device__ __forceinline__ void ldsm_x4(uint32_t* r, uint32_t addr) {
    asm volatile("ldmatrix.sync.aligned.m8n8.x4.shared.b16 {%0,%1,%2,%3}, [%4];"
                 : "=r"(r[0]), "=r"(r[1]), "=r"(r[2]), "=r"(r[3]) : "r"(addr));
}
__device__ __forceinline__ void ldsm_x4t(uint32_t* r, uint32_t addr) {
    asm volatile("ldmatrix.sync.aligned.m8n8.x4.trans.shared.b16 {%0,%1,%2,%3}, [%4];"
                 : "=r"(r[0]), "=r"(r[1]), "=r"(r[2]), "=r"(r[3]) : "r"(addr));
}
__device__ __forceinline__ void mma_f16(float* c, const uint32_t* a, uint32_t b0, uint32_t b1) {
    asm volatile("mma.sync.aligned.m16n8k16.row.col.f32.f16.f16.f32 "
                 "{%0,%1,%2,%3}, {%4,%5,%6,%7}, {%8,%9}, {%0,%1,%2,%3};"
                 : "+f"(c[0]), "+f"(c[1]), "+f"(c[2]), "+f"(c[3])
                 : "r"(a[0]), "r"(a[1]), "r"(a[2]), "r"(a[3]), "r"(b0), "r"(b1));
}

// ---------------------------------------------------------------------------
// Kernel 0a: main weights -> fp16
// ---------------------------------------------------------------------------
__global__ __launch_bounds__(256) void wconv_kernel(const float* __restrict__ w) {
    int i = blockIdx.x * 256 + threadIdx.x;
    if (i >= COUT * KDIM) return;
    g_W[i] = __float2half_rn(w[i]);
}

// Kernel 0b: offset weights -> fp16, padded to MOFF rows (k = ci*9+kk order)
__global__ __launch_bounds__(256) void wcvt_off_kernel(const float* __restrict__ ow) {
    int i = blockIdx.x * 256 + threadIdx.x;
    if (i >= MOFF * KDIM) return;
    g_Woff[i] = (i < OCH * KDIM) ? __float2half_rn(ow[i]) : __float2half_rn(0.0f);
}

// ---------------------------------------------------------------------------
// Kernel 1: S0 = zero-offset im2col of x, fp16. 2 pixels per thread.
// ---------------------------------------------------------------------------
__global__ __launch_bounds__(256) void s0_kernel(const float* __restrict__ x)
{
    const int pp = blockIdx.x * 256 + threadIdx.x;
    if (pp >= P / 2) return;
    const int b   = blockIdx.y;
    const int kk  = blockIdx.z / CISPL;
    const int ci0 = (blockIdx.z % CISPL) * CIH;

    const int p0 = pp * 2;
    const int ho = p0 / WW;
    const int wo = p0 % WW;
    const int dy = kk / 3 - 1;
    const int dx = kk % 3 - 1;
    const int y  = ho + dy;
    const bool vy  = (y >= 0 && y < HH);
    const int x0c = wo + dx;
    const int x1c = wo + 1 + dx;
    const bool v0 = vy && (x0c >= 0 && x0c < WW);
    const bool v1 = vy && (x1c >= 0 && x1c < WW);
    const int idx0 = (vy ? y * WW : 0) + (v0 ? x0c : 0);
    const int idx1 = (vy ? y * WW : 0) + (v1 ? x1c : 0);

    const float* xb = x + ((size_t)(b * CIN + ci0)) * P;
    __half2* sp = (__half2*)(g_S0 + (size_t)(ci0 * KK9 + kk) * NTOT + (size_t)b * P + p0);
    const size_t srow2 = (size_t)KK9 * NTOT / 2;

#pragma unroll 8
    for (int ci = 0; ci < CIH; ci++) {
        const float* xc = xb + (size_t)ci * P;
        float a = v0 ? __ldg(xc + idx0) : 0.0f;
        float c = v1 ? __ldg(xc + idx1) : 0.0f;
        sp[(size_t)ci * srow2] = __floats2half2_rn(a, c);
    }
}

// ---------------------------------------------------------------------------
// Kernel 2: offset GEMM (K-split x2): partial[ks][oc][n] = sum_{k in half}
// Woff[oc][k]*S0[k][n] (+ bias in split 0). grid (196, KSPL).
// ---------------------------------------------------------------------------
__global__ __launch_bounds__(128) void offgemm_kernel(const float* __restrict__ off_b)
{
    extern __shared__ char smem[];
    const uint32_t sb = smem_u32(smem);
    const int tid  = threadIdx.x;
    const int wid  = tid >> 5;
    const int lane = tid & 31;
    const int n0   = blockIdx.x * BN;
    const int ks   = blockIdx.y;
    const int kbase = ks * NKCH * BK;

    float acc[2][2][4];
#pragma unroll
    for (int i = 0; i < 2; i++)
#pragma unroll
        for (int j = 0; j < 2; j++)
#pragma unroll
            for (int q = 0; q < 4; q++) acc[i][j][q] = 0.0f;

    const __half* pS0 = g_S0 + n0;

    const int lrow  = lane & 15;
    const int lhalf = lane >> 4;
    const uint32_t a_base = (uint32_t)lrow * A_ROWB + lhalf * 16;
    const uint32_t b_base = (uint32_t)lrow * B_ROWB + (uint32_t)(wid * 16 + lhalf * 8) * 2;

    auto load_stage = [&](uint32_t st, int k0) {
#pragma unroll
        for (int it = 0; it < 2; it++) {
            int idx = it * 128 + tid;
            int row = idx >> 3;
            int c   = idx & 7;
            cp16(st + row * A_ROWB + c * 16, g_Woff + (size_t)row * KDIM + k0 + c * 8);
        }
#pragma unroll
        for (int it = 0; it < 4; it++) {
            int idx = it * 128 + tid;
            int row = idx >> 3;
            int c   = idx & 7;
            cp16(st + OB_OFF + row * B_ROWB + c * 16, pS0 + (size_t)(k0 + row) * NTOT + c * 8);
        }
    };

    load_stage(sb, kbase);
    cp_commit();

#pragma unroll 1
    for (int kc = 0; kc < NKCH; kc++) {
        const uint32_t buf = sb + (uint32_t)(kc & 1) * OBUF_BYTES;
        if (kc < NKCH - 1) {
            load_stage(sb + (uint32_t)((kc + 1) & 1) * OBUF_BYTES, kbase + (kc + 1) * BK);
            cp_commit();
            cp_wait1();
        } else {
            cp_wait0();
        }
        __syncthreads();

#pragma unroll
        for (int kk = 0; kk < 4; kk++) {
            uint32_t A[2][4], B[4];
#pragma unroll
            for (int mt = 0; mt < 2; mt++)
                ldsm_x4(A[mt], buf + a_base + (uint32_t)mt * 16 * A_ROWB + kk * 32);
            ldsm_x4t(B, buf + OB_OFF + b_base + (uint32_t)kk * 16 * B_ROWB);
#pragma unroll
            for (int mt = 0; mt < 2; mt++)
#pragma unroll
                for (int h = 0; h < 2; h++)
                    mma_f16(acc[mt][h], A[mt], B[2*h], B[2*h+1]);
        }
        __syncthreads();
    }

    float* op = g_OffP + (size_t)ks * OCH * NTOT;
    const int g = lane >> 2;
    const int t = lane & 3;
#pragma unroll
    for (int mt = 0; mt < 2; mt++) {
        int r0 = mt * 16 + g;
        int r1 = r0 + 8;
        float b0 = (ks == 0 && r0 < OCH) ? off_b[r0] : 0.0f;
        float b1 = (ks == 0 && r1 < OCH) ? off_b[r1] : 0.0f;
#pragma unroll
        for (int nt = 0; nt < 2; nt++) {
            int col = n0 + wid * 16 + nt * 8 + 2 * t;
            if (r0 < OCH) {
                op[(size_t)r0 * NTOT + col]     = acc[mt][nt][0] + b0;
                op[(size_t)r0 * NTOT + col + 1] = acc[mt][nt][1] + b0;
            }
            if (r1 < OCH) {
                op[(size_t)r1 * NTOT + col]     = acc[mt][nt][2] + b1;
                op[(size_t)r1 * NTOT + col + 1] = acc[mt][nt][3] + b1;
            }
        }
    }
}

// ---------------------------------------------------------------------------
// Kernel 3: bilinear sampling -> fp16 S[k=ci*9+kk][n=b*P+p]
// offsets = sum of KSPL partials.
// ---------------------------------------------------------------------------
__global__ __launch_bounds__(256) void sample_kernel(const float* __restrict__ x)
{
    const int tid = threadIdx.x;
    const int p   = blockIdx.x * 256 + tid;
    if (p >= P) return;
    const int b   = blockIdx.y;
    const int kk  = blockIdx.z / CISPL;
    const int ci0 = (blockIdx.z % CISPL) * CIH;

    const int n = b * P + p;
    const float offy = __ldg(g_OffP + (size_t)(2 * kk)     * NTOT + n)
                     + __ldg(g_OffP + (size_t)(OCH + 2 * kk)     * NTOT + n);
    const float offx = __ldg(g_OffP + (size_t)(2 * kk + 1) * NTOT + n)
                     + __ldg(g_OffP + (size_t)(OCH + 2 * kk + 1) * NTOT + n);

    const int ho = p / WW;
    const int wo = p % WW;
    const float py = (float)(ho - 1 + kk / 3) + offy;
    const float px = (float)(wo - 1 + kk % 3) + offx;
    const float fy = floorf(py), fx = floorf(px);
    const int y0 = (int)fy, x0 = (int)fx;
    const int y1 = y0 + 1,  x1 = x0 + 1;
    const float ty = py - fy, tx = px - fx;

    float w00 = (1.0f - ty) * (1.0f - tx);
    float w01 = (1.0f - ty) * tx;
    float w10 = ty * (1.0f - tx);
    float w11 = ty * tx;

    const bool vy0 = (y0 >= 0 && y0 < HH), vy1 = (y1 >= 0 && y1 < HH);
    const bool vx0 = (x0 >= 0 && x0 < WW), vx1 = (x1 >= 0 && x1 < WW);
    w00 *= (vy0 && vx0) ? 1.0f : 0.0f;
    w01 *= (vy0 && vx1) ? 1.0f : 0.0f;
    w10 *= (vy1 && vx0) ? 1.0f : 0.0f;
    w11 *= (vy1 && vx1) ? 1.0f : 0.0f;

    const int cy0 = min(max(y0, 0), HH - 1), cy1 = min(max(y1, 0), HH - 1);
    const int cx0 = min(max(x0, 0), WW - 1), cx1 = min(max(x1, 0), WW - 1);
    const int i00 = cy0 * WW + cx0, i01 = cy0 * WW + cx1;
    const int i10 = cy1 * WW + cx0, i11 = cy1 * WW + cx1;

    const float* xb = x + ((size_t)(b * CIN + ci0)) * P;
    const size_t base = (size_t)(ci0 * KK9 + kk) * NTOT + (size_t)n;
    const size_t srow = (size_t)KK9 * NTOT;

#pragma unroll 8
    for (int ci = 0; ci < CIH; ci++) {
        const float* xc = xb + (size_t)ci * P;
        float v = w00 * __ldg(xc + i00) + w01 * __ldg(xc + i01)
                + w10 * __ldg(xc + i10) + w11 * __ldg(xc + i11);
        g_S[base + (size_t)ci * srow] = __float2half_rn(v);
    }
}

// ---------------------------------------------------------------------------
// Kernel 4: main fp16 GEMM (proven config).
// ---------------------------------------------------------------------------
__global__ __launch_bounds__(128, 3) void gemm_mma_kernel(float* __restrict__ out)
{
    extern __shared__ char smem[];
    const uint32_t sb = smem_u32(smem);
    const int tid  = threadIdx.x;
    const int wid  = tid >> 5;
    const int lane = tid & 31;
    const int wm   = wid & 1;
    const int wn   = wid >> 1;
    const int n0   = blockIdx.x * BN;
    const int m0   = blockIdx.y * BM;

    float acc[4][4][4];
#pragma unroll
    for (int i = 0; i < 4; i++)
#pragma unroll
        for (int j = 0; j < 4; j++)
#pragma unroll
            for (int q = 0; q < 4; q++) acc[i][j][q] = 0.0f;

    const __half* pW = g_W + (size_t)m0 * KDIM;
    const __half* pS = g_S + n0;

    const int lrow  = lane & 15;
    const int lhalf = lane >> 4;
    const uint32_t a_base = (uint32_t)(wm * 64 + lrow) * A_ROWB + lhalf * 16;
    const uint32_t b_base = (uint32_t)lrow * B_ROWB + (uint32_t)(wn * 32 + lhalf * 8) * 2;

    auto load_stage = [&](uint32_t st, int k0) {
#pragma unroll
        for (int it = 0; it < 8; it++) {
            int idx = it * 128 + tid;
            int row = idx >> 3;
            int c   = idx & 7;
            cp16(st + row * A_ROWB + c * 16, pW + (size_t)row * KDIM + k0 + c * 8);
        }
#pragma unroll
        for (int it = 0; it < 4; it++) {
            int idx = it * 128 + tid;
            int row = idx >> 3;
            int c   = idx & 7;
            cp16(st + B_OFF + row * B_ROWB + c * 16, pS + (size_t)(k0 + row) * NTOT + c * 8);
        }
    };

    load_stage(sb, 0);
    cp_commit();

#pragma unroll 1
    for (int kc = 0; kc < NKC; kc++) {
        const uint32_t buf = sb + (uint32_t)(kc & 1) * BUF_BYTES;
        if (kc < NKC - 1) {
            load_stage(sb + (uint32_t)((kc + 1) & 1) * BUF_BYTES, (kc + 1) * BK);
            cp_commit();
            cp_wait1();
        } else {
            cp_wait0();
        }
        __syncthreads();

#pragma unroll
        for (int kk = 0; kk < 4; kk++) {
            uint32_t A[4][4], B[2][4];
#pragma unroll
            for (int mt = 0; mt < 4; mt++)
                ldsm_x4(A[mt], buf + a_base + (uint32_t)mt * 16 * A_ROWB + kk * 32);
#pragma unroll
            for (int bq = 0; bq < 2; bq++)
                ldsm_x4t(B[bq], buf + B_OFF + b_base + (uint32_t)kk * 16 * B_ROWB + bq * 32);
#pragma unroll
            for (int mt = 0; mt < 4; mt++) {
#pragma unroll
                for (int bq = 0; bq < 2; bq++) {
#pragma unroll
                    for (int h = 0; h < 2; h++) {
                        int nt = bq * 2 + h;
                        mma_f16(acc[mt][nt], A[mt], B[bq][2*h], B[bq][2*h+1]);
                    }
                }
            }
        }
        __syncthreads();
    }

    const int g = lane >> 2;
    const int t = lane & 3;
    const int bidx = n0 / P;
    const int pofs = n0 % P;
#pragma unroll
    for (int mt = 0; mt < 4; mt++) {
        int mrow = m0 + wm * 64 + mt * 16 + g;
        float* r0 = out + ((size_t)(bidx * COUT + mrow)) * P + pofs;
        float* r1 = r0 + 8 * P;
#pragma unroll
        for (int nt = 0; nt < 4; nt++) {
            int col = wn * 32 + nt * 8 + 2 * t;
            *(float2*)(r0 + col) = make_float2(acc[mt][nt][0], acc[mt][nt][1]);
            *(float2*)(r1 + col) = make_float2(acc[mt][nt][2], acc[mt][nt][3]);
        }
    }
}

// ---------------------------------------------------------------------------
extern "C" void kernel_launch(void* const* d_in, const int* in_sizes, int n_in,
                              void* d_out, int out_size)
{
    const float* x     = (const float*)d_in[0];
    const float* wgt   = (const float*)d_in[1];
    const float* off_w = (const float*)d_in[2];
    const float* off_b = (const float*)d_in[3];
    float* out = (float*)d_out;

    cudaFuncSetAttribute(gemm_mma_kernel, cudaFuncAttributeMaxDynamicSharedMemorySize, SMEM_TOTAL);
    cudaFuncSetAttribute(offgemm_kernel, cudaFuncAttributeMaxDynamicSharedMemorySize, OSMEM_TOTAL);

    wconv_kernel<<<(COUT * KDIM + 255) / 256, 256>>>(wgt);
    wcvt_off_kernel<<<(MOFF * KDIM + 255) / 256, 256>>>(off_w);

    dim3 g0((P / 2 + 255) / 256, BB, KK9 * CISPL);
    s0_kernel<<<g0, 256>>>(x);

    dim3 g1(NTOT / BN, KSPL);
    offgemm_kernel<<<g1, 128, OSMEM_TOTAL>>>(off_b);

    dim3 g2((P + 255) / 256, BB, KK9 * CISPL);
    sample_kernel<<<g2, 256>>>(x);

    dim3 g3(NTOT / BN, COUT / BM);
    gemm_mma_kernel<<<g3, 128, SMEM_TOTAL>>>(out);
}